// round 8
// baseline (speedup 1.0000x reference)
#include <cuda_runtime.h>
#include <cstdint>

#define N_NODES 100000
#define N_EDGES 1600000
#define NBLK 391          // ceil(N_NODES/256)
#define FULLM 0xFFFFFFFFu

// ---------------- device scratch ----------------
// g_h doubles as: (a) prescaled 32-dim input buffer for layer 1,
// (b) 64-dim GEMM output for layers 2/3.
__device__ float g_h[(size_t)N_NODES * 64];
__device__ float g_y[(size_t)N_NODES * 64];
__device__ float g_a[(size_t)N_NODES * 32];     // aggregated 32-dim buf
__device__ int   g_cnt[N_NODES];
__device__ float g_dinv[N_NODES];
__device__ int   g_offs[N_NODES + 1];
__device__ int   g_rank[N_EDGES];               // rank of edge within its dst row
__device__ int   g_srcl[N_EDGES];               // CSR src indices
__device__ int   g_bsum[512];
__device__ int   g_boff[512];
__device__ int   g_is64;

// ---------------- edge index accessors (int32 vs int64, guarded) ----------
__device__ __forceinline__ int load_idx(const void* ei, size_t pos, int is64) {
    long long v;
    if (is64) v = ((const long long*)ei)[pos];
    else      v = ((const int*)ei)[pos];
    if (v < 0) v = 0;
    if (v >= N_NODES) v = N_NODES - 1;
    return (int)v;
}

__global__ void detect_k(const int* __restrict__ ei32) {
    int lane = threadIdx.x;
    int nz = (ei32[2 * lane + 1] != 0);
    unsigned m = __ballot_sync(FULLM, nz);
    if (lane == 0) g_is64 = (m == 0) ? 1 : 0;
}

// count in-degree AND record each edge's rank within its destination row
__global__ void count_k(const void* __restrict__ ei) {
    int e = blockIdx.x * blockDim.x + threadIdx.x;
    if (e < N_EDGES) {
        int d = load_idx(ei, (size_t)N_EDGES + e, g_is64);
        g_rank[e] = atomicAdd(&g_cnt[d], 1);
    }
}

// ---- block sums (+ fused dinv computation) ----
__global__ void bsum_k() {
    __shared__ int ws[8];
    int i = blockIdx.x * 256 + threadIdx.x;
    int c = (i < N_NODES) ? g_cnt[i] : 0;
    if (i < N_NODES) g_dinv[i] = rsqrtf((float)c + 1.0f);
    int v = c;
    int lane = threadIdx.x & 31, wid = threadIdx.x >> 5;
#pragma unroll
    for (int d = 16; d > 0; d >>= 1) v += __shfl_down_sync(FULLM, v, d);
    if (lane == 0) ws[wid] = v;
    __syncthreads();
    if (wid == 0) {
        int s = (lane < 8) ? ws[lane] : 0;
#pragma unroll
        for (int d = 4; d > 0; d >>= 1) s += __shfl_down_sync(FULLM, s, d);
        if (lane == 0) g_bsum[blockIdx.x] = s;
    }
}

__global__ void bscan_k() {
    __shared__ int ts[512];
    int t = threadIdx.x;
    int v = (t < NBLK) ? g_bsum[t] : 0;
    ts[t] = v;
    __syncthreads();
    for (int d = 1; d < 512; d <<= 1) {
        int u = (t >= d) ? ts[t - d] : 0;
        __syncthreads();
        ts[t] += u;
        __syncthreads();
    }
    if (t < NBLK) g_boff[t] = ts[t] - v;
    if (t == NBLK - 1) g_offs[N_NODES] = ts[t];
}

__global__ void offs_k() {
    __shared__ int ts[256];
    int i = blockIdx.x * 256 + threadIdx.x;
    int t = threadIdx.x;
    int v = (i < N_NODES) ? g_cnt[i] : 0;
    ts[t] = v;
    __syncthreads();
    for (int d = 1; d < 256; d <<= 1) {
        int u = (t >= d) ? ts[t - d] : 0;
        __syncthreads();
        ts[t] += u;
        __syncthreads();
    }
    if (i < N_NODES) g_offs[i] = g_boff[blockIdx.x] + ts[t] - v;
}

// scatter src into CSR slots — no atomics (rank precomputed)
__global__ void fill_k(const void* __restrict__ ei) {
    int e = blockIdx.x * blockDim.x + threadIdx.x;
    if (e < N_EDGES) {
        int is64 = g_is64;
        int s = load_idx(ei, e, is64);
        int d = load_idx(ei, (size_t)N_EDGES + e, is64);
        g_srcl[g_offs[d] + g_rank[e]] = s;
    }
}

// x' = dinv[i] * x  (row-scaled input), float4 vectorized
__global__ void scale_k(const float* __restrict__ x, float* __restrict__ xs) {
    int i = blockIdx.x * blockDim.x + threadIdx.x;
    if (i < N_NODES * 8) {
        int node = i >> 3;
        float dv = g_dinv[node];
        float4 v = reinterpret_cast<const float4*>(x)[i];
        v.x *= dv; v.y *= dv; v.z *= dv; v.w *= dv;
        reinterpret_cast<float4*>(xs)[i] = v;
    }
}

// ---------------- GEMM: out[N,FOUT] = in[N,FIN] @ W^T, optional bias+relu or dinv-scale
template<int FIN, int FOUT, bool BR, bool SCALE>
__global__ void gemm_k(const float* __restrict__ x, const float* __restrict__ W,
                       const float* __restrict__ bias, float* __restrict__ h) {
    constexpr int TPR = FOUT / 4;
    constexpr int RPB = 256 / TPR;
    __shared__ float Ws[FIN * FOUT];
    for (int i = threadIdx.x; i < FIN * FOUT; i += 256) {
        int f = i / FIN, k = i % FIN;
        Ws[k * FOUT + f] = W[i];
    }
    __syncthreads();

    int r  = threadIdx.x / TPR;
    int c0 = (threadIdx.x % TPR) * 4;
    int row = blockIdx.x * RPB + r;
    if (row >= N_NODES) return;

    const float4* __restrict__ xr = reinterpret_cast<const float4*>(x + (size_t)row * FIN);
    float a0 = 0.f, a1 = 0.f, a2 = 0.f, a3 = 0.f;
#pragma unroll
    for (int k4 = 0; k4 < FIN / 4; k4++) {
        float4 xv = xr[k4];
        const float4 w0 = *reinterpret_cast<const float4*>(&Ws[(4 * k4 + 0) * FOUT + c0]);
        const float4 w1 = *reinterpret_cast<const float4*>(&Ws[(4 * k4 + 1) * FOUT + c0]);
        const float4 w2 = *reinterpret_cast<const float4*>(&Ws[(4 * k4 + 2) * FOUT + c0]);
        const float4 w3 = *reinterpret_cast<const float4*>(&Ws[(4 * k4 + 3) * FOUT + c0]);
        a0 = fmaf(xv.x, w0.x, a0); a1 = fmaf(xv.x, w0.y, a1);
        a2 = fmaf(xv.x, w0.z, a2); a3 = fmaf(xv.x, w0.w, a3);
        a0 = fmaf(xv.y, w1.x, a0); a1 = fmaf(xv.y, w1.y, a1);
        a2 = fmaf(xv.y, w1.z, a2); a3 = fmaf(xv.y, w1.w, a3);
        a0 = fmaf(xv.z, w2.x, a0); a1 = fmaf(xv.z, w2.y, a1);
        a2 = fmaf(xv.z, w2.z, a2); a3 = fmaf(xv.z, w2.w, a3);
        a0 = fmaf(xv.w, w3.x, a0); a1 = fmaf(xv.w, w3.y, a1);
        a2 = fmaf(xv.w, w3.z, a2); a3 = fmaf(xv.w, w3.w, a3);
    }
    if (BR) {
        a0 = fmaxf(a0 + bias[c0 + 0], 0.f);
        a1 = fmaxf(a1 + bias[c0 + 1], 0.f);
        a2 = fmaxf(a2 + bias[c0 + 2], 0.f);
        a3 = fmaxf(a3 + bias[c0 + 3], 0.f);
    }
    if (SCALE) {
        float dv = g_dinv[row];
        a0 *= dv; a1 *= dv; a2 *= dv; a3 *= dv;
    }
    *reinterpret_cast<float4*>(&h[(size_t)row * FOUT + c0]) =
        make_float4(a0, a1, a2, a3);
}

// ---------------- agg F=64: coalesced src-block load + shfl-distributed gathers
// 16 lanes x float4 per edge, 2 edges per k-step; 32 srcs fetched per warp LDG
template<bool BR>
__global__ void agg64_k(const float* __restrict__ h, const float* __restrict__ bias,
                        float* __restrict__ out) {
    int node = (blockIdx.x * blockDim.x + threadIdx.x) >> 5;
    int lane = threadIdx.x & 31;
    if (node >= N_NODES) return;
    int half = lane >> 4;
    int fl   = lane & 15;
    const float4* __restrict__ h4 = reinterpret_cast<const float4*>(h);

    int beg = g_offs[node];
    int end = g_offs[node + 1];

    float ax = 0.f, ay = 0.f, az = 0.f, aw = 0.f;
    for (int base = beg; base < end; base += 32) {
        int idx = base + lane;
        int sv = (idx < end) ? g_srcl[idx] : 0;
        int cnt = end - base; if (cnt > 32) cnt = 32;
        int k = 0;
#pragma unroll 4
        for (; k + 2 <= cnt; k += 2) {
            int s = __shfl_sync(FULLM, sv, k + half);
            float4 v = h4[(size_t)s * 16 + fl];
            ax += v.x; ay += v.y; az += v.z; aw += v.w;
        }
        if (k < cnt) {                       // odd leftover: half 0 lanes only
            int s = __shfl_sync(FULLM, sv, k);
            if (half == 0) {
                float4 v = h4[(size_t)s * 16 + fl];
                ax += v.x; ay += v.y; az += v.z; aw += v.w;
            }
        }
    }

    ax += __shfl_xor_sync(FULLM, ax, 16);
    ay += __shfl_xor_sync(FULLM, ay, 16);
    az += __shfl_xor_sync(FULLM, az, 16);
    aw += __shfl_xor_sync(FULLM, aw, 16);

    if (half == 0) {
        float dv = g_dinv[node];
        float4 vs = h4[(size_t)node * 16 + fl];
        ax = (ax + vs.x) * dv; ay = (ay + vs.y) * dv;
        az = (az + vs.z) * dv; aw = (aw + vs.w) * dv;
        if (BR) {
            const float4 bv = reinterpret_cast<const float4*>(bias)[fl];
            ax = fmaxf(ax + bv.x, 0.f); ay = fmaxf(ay + bv.y, 0.f);
            az = fmaxf(az + bv.z, 0.f); aw = fmaxf(aw + bv.w, 0.f);
        }
        reinterpret_cast<float4*>(out)[(size_t)node * 16 + fl] =
            make_float4(ax, ay, az, aw);
    }
}

// ---------------- agg F=32: coalesced src-block load, 8 lanes x float4 per edge,
// 4 edges per k-step
template<bool BR>
__global__ void agg32_k(const float* __restrict__ h, const float* __restrict__ bias,
                        float* __restrict__ out) {
    int node = (blockIdx.x * blockDim.x + threadIdx.x) >> 5;
    int lane = threadIdx.x & 31;
    if (node >= N_NODES) return;
    int q  = lane >> 3;
    int fl = lane & 7;
    const float4* __restrict__ h4 = reinterpret_cast<const float4*>(h);

    int beg = g_offs[node];
    int end = g_offs[node + 1];

    float ax = 0.f, ay = 0.f, az = 0.f, aw = 0.f;
    for (int base = beg; base < end; base += 32) {
        int idx = base + lane;
        int sv = (idx < end) ? g_srcl[idx] : 0;
        int cnt = end - base; if (cnt > 32) cnt = 32;
        int k = 0;
#pragma unroll 4
        for (; k + 4 <= cnt; k += 4) {
            int s = __shfl_sync(FULLM, sv, k + q);
            float4 v = h4[(size_t)s * 8 + fl];
            ax += v.x; ay += v.y; az += v.z; aw += v.w;
        }
        for (; k < cnt; k++) {               // up to 3 leftovers: group 0 only
            int s = __shfl_sync(FULLM, sv, k);
            if (q == 0) {
                float4 v = h4[(size_t)s * 8 + fl];
                ax += v.x; ay += v.y; az += v.z; aw += v.w;
            }
        }
    }

    ax += __shfl_xor_sync(FULLM, ax, 8);
    ay += __shfl_xor_sync(FULLM, ay, 8);
    az += __shfl_xor_sync(FULLM, az, 8);
    aw += __shfl_xor_sync(FULLM, aw, 8);
    ax += __shfl_xor_sync(FULLM, ax, 16);
    ay += __shfl_xor_sync(FULLM, ay, 16);
    az += __shfl_xor_sync(FULLM, az, 16);
    aw += __shfl_xor_sync(FULLM, aw, 16);

    if (q == 0) {
        float dv = g_dinv[node];
        float4 vs = h4[(size_t)node * 8 + fl];
        ax = (ax + vs.x) * dv; ay = (ay + vs.y) * dv;
        az = (az + vs.z) * dv; aw = (aw + vs.w) * dv;
        if (BR) {
            const float4 bv = reinterpret_cast<const float4*>(bias)[fl];
            ax = fmaxf(ax + bv.x, 0.f); ay = fmaxf(ay + bv.y, 0.f);
            az = fmaxf(az + bv.z, 0.f); aw = fmaxf(aw + bv.w, 0.f);
        }
        reinterpret_cast<float4*>(out)[(size_t)node * 8 + fl] =
            make_float4(ax, ay, az, aw);
    }
}

// ---------------- launch ----------------
extern "C" void kernel_launch(void* const* d_in, const int* in_sizes, int n_in,
                              void* d_out, int out_size) {
    const float* x  = (const float*)d_in[0];
    const void*  ei = d_in[1];
    const float* W1 = (const float*)d_in[2];
    const float* b1 = (const float*)d_in[3];
    const float* W2 = (const float*)d_in[4];
    const float* b2 = (const float*)d_in[5];
    const float* W3 = (const float*)d_in[6];
    const float* b3 = (const float*)d_in[7];
    float* out = (float*)d_out;

    void *ph, *py, *pa, *pc;
    cudaGetSymbolAddress(&ph, g_h);
    cudaGetSymbolAddress(&py, g_y);
    cudaGetSymbolAddress(&pa, g_a);
    cudaGetSymbolAddress(&pc, g_cnt);
    float* h  = (float*)ph;
    float* y  = (float*)py;
    float* a  = (float*)pa;
    float* xs = h;   // layer-1 prescaled input lives in g_h (idle until layer 2)

    const int TB = 256;
    const int WGRID = (N_NODES * 32 + TB - 1) / TB;
    const int EGRID = (N_EDGES + TB - 1) / TB;

    // dtype detect + CSR build (rank-based, no cursor atomics)
    detect_k<<<1, 32>>>((const int*)ei);
    cudaMemsetAsync(pc, 0, N_NODES * sizeof(int));
    count_k<<<EGRID, TB>>>(ei);
    bsum_k <<<NBLK, TB>>>();       // also computes dinv
    bscan_k<<<1, 512>>>();
    offs_k <<<NBLK, TB>>>();
    fill_k <<<EGRID, TB>>>(ei);

    // Layer 1: x' = dinv*x (in g_h); a = dinv*(sum x'[s] + x'[d]); y1 = relu(a@W1^T + b1)
    scale_k<<<(N_NODES * 8 + TB - 1) / TB, TB>>>(x, xs);
    agg32_k<false><<<WGRID, TB>>>(xs, nullptr, a);
    gemm_k<32, 64, true, false><<<N_NODES / 16, TB>>>(a, W1, b1, y);
    // Layer 2: h' = dinv*(y1@W2^T); y2 = relu(dinv*(sum h'[s] + h'[d]) + b2)
    gemm_k<64, 64, false, true><<<N_NODES / 16, TB>>>(y, W2, nullptr, h);
    agg64_k<true><<<WGRID, TB>>>(h, b2, y);
    // Layer 3: h' = dinv*(y2@W3^T); out = relu(dinv*(sum h'[s] + h'[d]) + b3)
    gemm_k<64, 32, false, true><<<N_NODES / 32, TB>>>(y, W3, nullptr, h);
    agg32_k<true><<<WGRID, TB>>>(h, b3, out);

    (void)in_sizes; (void)n_in; (void)out_size;
}

// round 9
// speedup vs baseline: 1.0792x; 1.0792x over previous
#include <cuda_runtime.h>
#include <cuda_fp16.h>
#include <cstdint>

#define N_NODES 100000
#define N_EDGES 1600000
#define NBLK 391          // ceil(N_NODES/256)
#define FULLM 0xFFFFFFFFu

// ---------------- device scratch ----------------
// g_hh (fp16) holds the gather operand: layer-1 prescaled x (32-dim rows),
// then layer-2/3 GEMM outputs (64/32-dim rows).
__device__ __half g_hh[(size_t)N_NODES * 64];
__device__ float  g_y[(size_t)N_NODES * 64];
__device__ float  g_a[(size_t)N_NODES * 32];    // aggregated 32-dim buf (fp32)
__device__ int    g_cnt[N_NODES];
__device__ float  g_dinv[N_NODES];
__device__ int    g_offs[N_NODES + 1];
__device__ int    g_rank[N_EDGES];              // rank of edge within its dst row
__device__ int    g_srcl[N_EDGES];              // CSR src indices
__device__ int    g_bsum[512];
__device__ int    g_boff[512];
__device__ int    g_is64;

// ---------------- edge index accessors (int32 vs int64, guarded) ----------
__device__ __forceinline__ int load_idx(const void* ei, size_t pos, int is64) {
    long long v;
    if (is64) v = ((const long long*)ei)[pos];
    else      v = ((const int*)ei)[pos];
    if (v < 0) v = 0;
    if (v >= N_NODES) v = N_NODES - 1;
    return (int)v;
}

__global__ void detect_k(const int* __restrict__ ei32) {
    int lane = threadIdx.x;
    int nz = (ei32[2 * lane + 1] != 0);
    unsigned m = __ballot_sync(FULLM, nz);
    if (lane == 0) g_is64 = (m == 0) ? 1 : 0;
}

// count in-degree AND record each edge's rank within its destination row
__global__ void count_k(const void* __restrict__ ei) {
    int e = blockIdx.x * blockDim.x + threadIdx.x;
    if (e < N_EDGES) {
        int d = load_idx(ei, (size_t)N_EDGES + e, g_is64);
        g_rank[e] = atomicAdd(&g_cnt[d], 1);
    }
}

// ---- block sums (+ fused dinv computation) ----
__global__ void bsum_k() {
    __shared__ int ws[8];
    int i = blockIdx.x * 256 + threadIdx.x;
    int c = (i < N_NODES) ? g_cnt[i] : 0;
    if (i < N_NODES) g_dinv[i] = rsqrtf((float)c + 1.0f);
    int v = c;
    int lane = threadIdx.x & 31, wid = threadIdx.x >> 5;
#pragma unroll
    for (int d = 16; d > 0; d >>= 1) v += __shfl_down_sync(FULLM, v, d);
    if (lane == 0) ws[wid] = v;
    __syncthreads();
    if (wid == 0) {
        int s = (lane < 8) ? ws[lane] : 0;
#pragma unroll
        for (int d = 4; d > 0; d >>= 1) s += __shfl_down_sync(FULLM, s, d);
        if (lane == 0) g_bsum[blockIdx.x] = s;
    }
}

__global__ void bscan_k() {
    __shared__ int ts[512];
    int t = threadIdx.x;
    int v = (t < NBLK) ? g_bsum[t] : 0;
    ts[t] = v;
    __syncthreads();
    for (int d = 1; d < 512; d <<= 1) {
        int u = (t >= d) ? ts[t - d] : 0;
        __syncthreads();
        ts[t] += u;
        __syncthreads();
    }
    if (t < NBLK) g_boff[t] = ts[t] - v;
    if (t == NBLK - 1) g_offs[N_NODES] = ts[t];
}

__global__ void offs_k() {
    __shared__ int ts[256];
    int i = blockIdx.x * 256 + threadIdx.x;
    int t = threadIdx.x;
    int v = (i < N_NODES) ? g_cnt[i] : 0;
    ts[t] = v;
    __syncthreads();
    for (int d = 1; d < 256; d <<= 1) {
        int u = (t >= d) ? ts[t - d] : 0;
        __syncthreads();
        ts[t] += u;
        __syncthreads();
    }
    if (i < N_NODES) g_offs[i] = g_boff[blockIdx.x] + ts[t] - v;
}

// scatter src into CSR slots — no atomics (rank precomputed)
__global__ void fill_k(const void* __restrict__ ei) {
    int e = blockIdx.x * blockDim.x + threadIdx.x;
    if (e < N_EDGES) {
        int is64 = g_is64;
        int s = load_idx(ei, e, is64);
        int d = load_idx(ei, (size_t)N_EDGES + e, is64);
        g_srcl[g_offs[d] + g_rank[e]] = s;
    }
}

// x' = half(dinv[i] * x), 4 features per thread
__global__ void scale_k(const float* __restrict__ x, __half* __restrict__ xs) {
    int i = blockIdx.x * blockDim.x + threadIdx.x;   // over N_NODES*8 quads
    if (i < N_NODES * 8) {
        int node = i >> 3;
        float dv = g_dinv[node];
        float4 v = reinterpret_cast<const float4*>(x)[i];
        __half2 h0 = __floats2half2_rn(v.x * dv, v.y * dv);
        __half2 h1 = __floats2half2_rn(v.z * dv, v.w * dv);
        uint2 u;
        u.x = *reinterpret_cast<uint32_t*>(&h0);
        u.y = *reinterpret_cast<uint32_t*>(&h1);
        reinterpret_cast<uint2*>(xs)[i] = u;
    }
}

// ---------------- GEMM: out[N,FOUT] = in[N,FIN] @ W^T
// BR: +bias+relu (fp32 out). OUTH: dinv-scale + fp16 out (gather operand).
template<int FIN, int FOUT, bool BR, bool OUTH>
__global__ void gemm_k(const float* __restrict__ x, const float* __restrict__ W,
                       const float* __restrict__ bias, void* __restrict__ hout) {
    constexpr int TPR = FOUT / 4;
    constexpr int RPB = 256 / TPR;
    __shared__ float Ws[FIN * FOUT];
    for (int i = threadIdx.x; i < FIN * FOUT; i += 256) {
        int f = i / FIN, k = i % FIN;
        Ws[k * FOUT + f] = W[i];
    }
    __syncthreads();

    int r  = threadIdx.x / TPR;
    int c0 = (threadIdx.x % TPR) * 4;
    int row = blockIdx.x * RPB + r;
    if (row >= N_NODES) return;

    const float4* __restrict__ xr = reinterpret_cast<const float4*>(x + (size_t)row * FIN);
    float a0 = 0.f, a1 = 0.f, a2 = 0.f, a3 = 0.f;
#pragma unroll
    for (int k4 = 0; k4 < FIN / 4; k4++) {
        float4 xv = xr[k4];
        const float4 w0 = *reinterpret_cast<const float4*>(&Ws[(4 * k4 + 0) * FOUT + c0]);
        const float4 w1 = *reinterpret_cast<const float4*>(&Ws[(4 * k4 + 1) * FOUT + c0]);
        const float4 w2 = *reinterpret_cast<const float4*>(&Ws[(4 * k4 + 2) * FOUT + c0]);
        const float4 w3 = *reinterpret_cast<const float4*>(&Ws[(4 * k4 + 3) * FOUT + c0]);
        a0 = fmaf(xv.x, w0.x, a0); a1 = fmaf(xv.x, w0.y, a1);
        a2 = fmaf(xv.x, w0.z, a2); a3 = fmaf(xv.x, w0.w, a3);
        a0 = fmaf(xv.y, w1.x, a0); a1 = fmaf(xv.y, w1.y, a1);
        a2 = fmaf(xv.y, w1.z, a2); a3 = fmaf(xv.y, w1.w, a3);
        a0 = fmaf(xv.z, w2.x, a0); a1 = fmaf(xv.z, w2.y, a1);
        a2 = fmaf(xv.z, w2.z, a2); a3 = fmaf(xv.z, w2.w, a3);
        a0 = fmaf(xv.w, w3.x, a0); a1 = fmaf(xv.w, w3.y, a1);
        a2 = fmaf(xv.w, w3.z, a2); a3 = fmaf(xv.w, w3.w, a3);
    }
    if (BR) {
        a0 = fmaxf(a0 + bias[c0 + 0], 0.f);
        a1 = fmaxf(a1 + bias[c0 + 1], 0.f);
        a2 = fmaxf(a2 + bias[c0 + 2], 0.f);
        a3 = fmaxf(a3 + bias[c0 + 3], 0.f);
    }
    if (OUTH) {
        float dv = g_dinv[row];
        __half2 h0 = __floats2half2_rn(a0 * dv, a1 * dv);
        __half2 h1 = __floats2half2_rn(a2 * dv, a3 * dv);
        uint2 u;
        u.x = *reinterpret_cast<uint32_t*>(&h0);
        u.y = *reinterpret_cast<uint32_t*>(&h1);
        reinterpret_cast<uint2*>(hout)[((size_t)row * FOUT + c0) >> 2] = u;
    } else {
        reinterpret_cast<float4*>(hout)[((size_t)row * FOUT + c0) >> 2] =
            make_float4(a0, a1, a2, a3);
    }
}

__device__ __forceinline__ void acc_half4(float& ax, float& ay, float& az, float& aw,
                                          uint2 u) {
    __half2 p0 = *reinterpret_cast<__half2*>(&u.x);
    __half2 p1 = *reinterpret_cast<__half2*>(&u.y);
    float2 f0 = __half22float2(p0);
    float2 f1 = __half22float2(p1);
    ax += f0.x; ay += f0.y; az += f1.x; aw += f1.y;
}

// ---------------- agg F=64 (fp16 in): 16 lanes x 4 halves per edge, 2 edges/iter
template<bool BR>
__global__ void agg64_k(const __half* __restrict__ h, const float* __restrict__ bias,
                        float* __restrict__ out) {
    int node = (blockIdx.x * blockDim.x + threadIdx.x) >> 5;
    int lane = threadIdx.x & 31;
    if (node >= N_NODES) return;
    int half = lane >> 4;
    int fl   = lane & 15;
    const uint2* __restrict__ h8 = reinterpret_cast<const uint2*>(h);

    int beg = g_offs[node];
    int end = g_offs[node + 1];

    float ax = 0.f, ay = 0.f, az = 0.f, aw = 0.f;
    int j = beg + half;
    for (; j + 2 < end; j += 4) {
        int s0 = g_srcl[j];
        int s1 = g_srcl[j + 2];
        uint2 u0 = h8[(size_t)s0 * 16 + fl];
        uint2 u1 = h8[(size_t)s1 * 16 + fl];
        acc_half4(ax, ay, az, aw, u0);
        acc_half4(ax, ay, az, aw, u1);
    }
    if (j < end) {
        int s = g_srcl[j];
        acc_half4(ax, ay, az, aw, h8[(size_t)s * 16 + fl]);
    }

    ax += __shfl_xor_sync(FULLM, ax, 16);
    ay += __shfl_xor_sync(FULLM, ay, 16);
    az += __shfl_xor_sync(FULLM, az, 16);
    aw += __shfl_xor_sync(FULLM, aw, 16);

    if (half == 0) {
        float dv = g_dinv[node];
        acc_half4(ax, ay, az, aw, h8[(size_t)node * 16 + fl]);   // self loop
        ax *= dv; ay *= dv; az *= dv; aw *= dv;
        if (BR) {
            const float4 bv = reinterpret_cast<const float4*>(bias)[fl];
            ax = fmaxf(ax + bv.x, 0.f); ay = fmaxf(ay + bv.y, 0.f);
            az = fmaxf(az + bv.z, 0.f); aw = fmaxf(aw + bv.w, 0.f);
        }
        reinterpret_cast<float4*>(out)[(size_t)node * 16 + fl] =
            make_float4(ax, ay, az, aw);
    }
}

// ---------------- agg F=32 (fp16 in): 8 lanes x 4 halves per edge, 4 edges/iter
template<bool BR>
__global__ void agg32_k(const __half* __restrict__ h, const float* __restrict__ bias,
                        float* __restrict__ out) {
    int node = (blockIdx.x * blockDim.x + threadIdx.x) >> 5;
    int lane = threadIdx.x & 31;
    if (node >= N_NODES) return;
    int q  = lane >> 3;
    int fl = lane & 7;
    const uint2* __restrict__ h8 = reinterpret_cast<const uint2*>(h);

    int beg = g_offs[node];
    int end = g_offs[node + 1];

    float ax = 0.f, ay = 0.f, az = 0.f, aw = 0.f;
    int j = beg + q;
    for (; j + 4 < end; j += 8) {
        int s0 = g_srcl[j];
        int s1 = g_srcl[j + 4];
        uint2 u0 = h8[(size_t)s0 * 8 + fl];
        uint2 u1 = h8[(size_t)s1 * 8 + fl];
        acc_half4(ax, ay, az, aw, u0);
        acc_half4(ax, ay, az, aw, u1);
    }
    if (j < end) {
        int s = g_srcl[j];
        acc_half4(ax, ay, az, aw, h8[(size_t)s * 8 + fl]);
    }

    ax += __shfl_xor_sync(FULLM, ax, 8);
    ay += __shfl_xor_sync(FULLM, ay, 8);
    az += __shfl_xor_sync(FULLM, az, 8);
    aw += __shfl_xor_sync(FULLM, aw, 8);
    ax += __shfl_xor_sync(FULLM, ax, 16);
    ay += __shfl_xor_sync(FULLM, ay, 16);
    az += __shfl_xor_sync(FULLM, az, 16);
    aw += __shfl_xor_sync(FULLM, aw, 16);

    if (q == 0) {
        float dv = g_dinv[node];
        acc_half4(ax, ay, az, aw, h8[(size_t)node * 8 + fl]);    // self loop
        ax *= dv; ay *= dv; az *= dv; aw *= dv;
        if (BR) {
            const float4 bv = reinterpret_cast<const float4*>(bias)[fl];
            ax = fmaxf(ax + bv.x, 0.f); ay = fmaxf(ay + bv.y, 0.f);
            az = fmaxf(az + bv.z, 0.f); aw = fmaxf(aw + bv.w, 0.f);
        }
        reinterpret_cast<float4*>(out)[(size_t)node * 8 + fl] =
            make_float4(ax, ay, az, aw);
    }
}

// ---------------- launch ----------------
extern "C" void kernel_launch(void* const* d_in, const int* in_sizes, int n_in,
                              void* d_out, int out_size) {
    const float* x  = (const float*)d_in[0];
    const void*  ei = d_in[1];
    const float* W1 = (const float*)d_in[2];
    const float* b1 = (const float*)d_in[3];
    const float* W2 = (const float*)d_in[4];
    const float* b2 = (const float*)d_in[5];
    const float* W3 = (const float*)d_in[6];
    const float* b3 = (const float*)d_in[7];
    float* out = (float*)d_out;

    void *phh, *py, *pa, *pc;
    cudaGetSymbolAddress(&phh, g_hh);
    cudaGetSymbolAddress(&py, g_y);
    cudaGetSymbolAddress(&pa, g_a);
    cudaGetSymbolAddress(&pc, g_cnt);
    __half* hh = (__half*)phh;
    float*  y  = (float*)py;
    float*  a  = (float*)pa;

    const int TB = 256;
    const int WGRID = (N_NODES * 32 + TB - 1) / TB;
    const int EGRID = (N_EDGES + TB - 1) / TB;

    // dtype detect + CSR build (rank-based, no cursor atomics)
    detect_k<<<1, 32>>>((const int*)ei);
    cudaMemsetAsync(pc, 0, N_NODES * sizeof(int));
    count_k<<<EGRID, TB>>>(ei);
    bsum_k <<<NBLK, TB>>>();       // also computes dinv
    bscan_k<<<1, 512>>>();
    offs_k <<<NBLK, TB>>>();
    fill_k <<<EGRID, TB>>>(ei);

    // Layer 1: hh = half(dinv*x); a = dinv*(sum hh[s] + hh[d]); y1 = relu(a@W1^T+b1)
    scale_k<<<(N_NODES * 8 + TB - 1) / TB, TB>>>(x, hh);
    agg32_k<false><<<WGRID, TB>>>(hh, nullptr, a);
    gemm_k<32, 64, true, false><<<N_NODES / 16, TB>>>(a, W1, b1, y);
    // Layer 2: hh = half(dinv*(y1@W2^T)); y2 = relu(dinv*(sum hh[s]+hh[d]) + b2)
    gemm_k<64, 64, false, true><<<N_NODES / 16, TB>>>(y, W2, nullptr, hh);
    agg64_k<true><<<WGRID, TB>>>(hh, b2, y);
    // Layer 3: hh = half(dinv*(y2@W3^T)); out = relu(dinv*(sum hh[s]+hh[d]) + b3)
    gemm_k<64, 32, false, true><<<N_NODES / 32, TB>>>(y, W3, nullptr, hh);
    agg32_k<true><<<WGRID, TB>>>(hh, b3, out);

    (void)in_sizes; (void)n_in; (void)out_size;
}